// round 1
// baseline (speedup 1.0000x reference)
#include <cuda_runtime.h>

#define NN 100000
#define EE 1600000
#define FD 128
#define CHUNK 1024
#define NCH ((NN + CHUNK - 1) / CHUNK)   // 98

// ---------------- device scratch (static, no allocation) ----------------
__device__ int   g_cnt[4][NN];           // 0: out_i, 1: in_i, 2: out_b, 3: in_b
__device__ float g_norm[4][NN];          // rsqrt(max(cnt,1))
__device__ int   g_rowptr[2][NN + 1];    // CSR by dst: 0=interacts, 1=behave
__device__ int   g_fill[2][NN];
__device__ int   g_col[2][EE];           // src indices per CSR slot
__device__ int   g_csums[2][NCH];
__device__ float g_H1[NN * FD];          // (x@W1_i)*nout_i ; reused as G=H@W2 in layer 2
__device__ float g_H1B[NN * FD];         // (x@W1_b)*nout_b
__device__ float g_H[NN * FD];           // conv1 output, pre-scaled by nout_i

// ---------------- prep kernels ----------------
__global__ void k_zero() {
    int i = blockIdx.x * blockDim.x + threadIdx.x;
    if (i < 4 * NN) ((int*)g_cnt)[i] = 0;
    else if (i < 6 * NN) ((int*)g_fill)[i - 4 * NN] = 0;
}

__global__ void k_hist(const int* __restrict__ si, const int* __restrict__ di,
                       const int* __restrict__ sb, const int* __restrict__ db) {
    int e = blockIdx.x * blockDim.x + threadIdx.x;
    if (e < EE) {
        atomicAdd(&g_cnt[0][si[e]], 1);
        atomicAdd(&g_cnt[1][di[e]], 1);
        atomicAdd(&g_cnt[2][sb[e]], 1);
        atomicAdd(&g_cnt[3][db[e]], 1);
    }
}

__global__ void k_norm() {
    int i = blockIdx.x * blockDim.x + threadIdx.x;
    if (i < NN) {
#pragma unroll
        for (int r = 0; r < 4; r++) {
            int c = g_cnt[r][i];
            if (c < 1) c = 1;
            g_norm[r][i] = rsqrtf((float)c);
        }
    }
}

// per-chunk sums of in-degree counts
__global__ void k_scanA() {
    int rel = blockIdx.y;
    const int* cnt = g_cnt[1 + 2 * rel];
    int base = blockIdx.x * CHUNK;
    int sum = 0;
    for (int i = threadIdx.x; i < CHUNK; i += 256) {
        int gi = base + i;
        sum += (gi < NN) ? cnt[gi] : 0;
    }
    __shared__ int sh[8];
    for (int o = 16; o; o >>= 1) sum += __shfl_down_sync(0xFFFFFFFFu, sum, o);
    if ((threadIdx.x & 31) == 0) sh[threadIdx.x >> 5] = sum;
    __syncthreads();
    if (threadIdx.x == 0) {
        int s = 0;
        for (int w = 0; w < 8; w++) s += sh[w];
        g_csums[rel][blockIdx.x] = s;
    }
}

// exclusive scan over the NCH chunk sums (tiny, serial in smem)
__global__ void k_scanB() {
    int rel = blockIdx.x;
    __shared__ int sh[NCH];
    if (threadIdx.x < NCH) sh[threadIdx.x] = g_csums[rel][threadIdx.x];
    __syncthreads();
    if (threadIdx.x == 0) {
        int acc = 0;
        for (int i = 0; i < NCH; i++) { int v = sh[i]; sh[i] = acc; acc += v; }
    }
    __syncthreads();
    if (threadIdx.x < NCH) g_csums[rel][threadIdx.x] = sh[threadIdx.x];
}

// per-chunk Hillis-Steele inclusive scan -> exclusive rowptr
__global__ void k_scanC() {
    int rel = blockIdx.y;
    const int* cnt = g_cnt[1 + 2 * rel];
    int* rp = g_rowptr[rel];
    int gi = blockIdx.x * CHUNK + threadIdx.x;
    int v = (gi < NN) ? cnt[gi] : 0;
    __shared__ int sh[CHUNK];
    sh[threadIdx.x] = v;
    __syncthreads();
    int val = v;
    for (int off = 1; off < CHUNK; off <<= 1) {
        int t2 = (threadIdx.x >= off) ? sh[threadIdx.x - off] : 0;
        __syncthreads();
        val += t2;
        sh[threadIdx.x] = val;
        __syncthreads();
    }
    int offc = g_csums[rel][blockIdx.x];
    if (gi < NN) rp[gi] = offc + val - v;
    if (gi == NN - 1) rp[NN] = offc + val;   // == EE
}

__global__ void k_csrfill(const int* __restrict__ si, const int* __restrict__ di,
                          const int* __restrict__ sb, const int* __restrict__ db) {
    int e = blockIdx.x * blockDim.x + threadIdx.x;
    if (e < EE) {
        int d = di[e];
        int p = g_rowptr[0][d] + atomicAdd(&g_fill[0][d], 1);
        g_col[0][p] = si[e];
        d = db[e];
        p = g_rowptr[1][d] + atomicAdd(&g_fill[1][d], 1);
        g_col[1][p] = sb[e];
    }
}

// ---------------- GEMM: [NN,128] @ [128,128], optional dual output ----------------
// MODE 0: X=x (param), Ya=g_H1 scaled by nout_i, Yb=g_H1B scaled by nout_b (dual)
// MODE 1: X=g_H (already pre-scaled), Ya=g_H1, no scale, single
template <int MODE>
__global__ __launch_bounds__(512) void k_gemm(const float* __restrict__ Xext,
                                              const float* __restrict__ Wa,
                                              const float* __restrict__ Wb) {
    __shared__ float xst[32][68];      // transposed x tile [k][row], padded
    __shared__ float was[32][128];
    __shared__ float wbs[32][128];

    const float* X = (MODE == 0) ? Xext : g_H;
    const int t  = threadIdx.x;
    const int c0 = (t & 31) * 4;       // 4 output cols
    const int rg = t >> 5;             // 0..15 -> 4 rows rg*4..rg*4+3
    const int bm = blockIdx.x * 64;

    float acc_a[4][4] = {};
    float acc_b[4][4] = {};

    for (int kc = 0; kc < 4; kc++) {
        const int k0 = kc * 32;
        for (int i = t; i < 32 * 128; i += 512) {
            int kk = i >> 7, c = i & 127;
            was[kk][c] = Wa[(k0 + kk) * 128 + c];
            if (MODE == 0) wbs[kk][c] = Wb[(k0 + kk) * 128 + c];
        }
        for (int i = t; i < 64 * 32; i += 512) {
            int row = i >> 5, kk = i & 31;
            int gm = bm + row;
            xst[kk][row] = (gm < NN) ? X[gm * 128 + k0 + kk] : 0.f;
        }
        __syncthreads();
#pragma unroll
        for (int kk = 0; kk < 32; kk++) {
            float4 xv = *(const float4*)&xst[kk][rg * 4];       // warp-broadcast
            float xr[4] = {xv.x, xv.y, xv.z, xv.w};
            float4 wv = *(const float4*)&was[kk][c0];
            float wr[4] = {wv.x, wv.y, wv.z, wv.w};
#pragma unroll
            for (int j = 0; j < 4; j++)
#pragma unroll
                for (int cc = 0; cc < 4; cc++)
                    acc_a[j][cc] += xr[j] * wr[cc];
            if (MODE == 0) {
                float4 wv2 = *(const float4*)&wbs[kk][c0];
                float wr2[4] = {wv2.x, wv2.y, wv2.z, wv2.w};
#pragma unroll
                for (int j = 0; j < 4; j++)
#pragma unroll
                    for (int cc = 0; cc < 4; cc++)
                        acc_b[j][cc] += xr[j] * wr2[cc];
            }
        }
        __syncthreads();
    }

#pragma unroll
    for (int j = 0; j < 4; j++) {
        int m = bm + rg * 4 + j;
        if (m < NN) {
            float sa = (MODE == 0) ? g_norm[0][m] : 1.f;
            float4 oa;
            oa.x = acc_a[j][0] * sa; oa.y = acc_a[j][1] * sa;
            oa.z = acc_a[j][2] * sa; oa.w = acc_a[j][3] * sa;
            *(float4*)&g_H1[m * 128 + c0] = oa;
            if (MODE == 0) {
                float sb_ = g_norm[2][m];
                float4 ob;
                ob.x = acc_b[j][0] * sb_; ob.y = acc_b[j][1] * sb_;
                ob.z = acc_b[j][2] * sb_; ob.w = acc_b[j][3] * sb_;
                *(float4*)&g_H1B[m * 128 + c0] = ob;
            }
        }
    }
}

// ---------------- SpMM: one block (128 threads) per node, thread = feature ----------------
__device__ __forceinline__ float gather_sum(const float* __restrict__ Hbuf,
                                            const int* __restrict__ col,
                                            int e, int e1, int t) {
    float acc = 0.f;
    for (; e + 4 <= e1; e += 4) {
        int s0 = col[e], s1 = col[e + 1], s2 = col[e + 2], s3 = col[e + 3];
        float v0 = Hbuf[s0 * 128 + t];
        float v1 = Hbuf[s1 * 128 + t];
        float v2 = Hbuf[s2 * 128 + t];
        float v3 = Hbuf[s3 * 128 + t];
        acc += (v0 + v1) + (v2 + v3);
    }
    for (; e < e1; e++) acc += Hbuf[col[e] * 128 + t];
    return acc;
}

__global__ void k_spmm1(const float* __restrict__ b1i, const float* __restrict__ b1b) {
    int v = blockIdx.x, t = threadIdx.x;
    float ai = gather_sum(g_H1,  g_col[0], g_rowptr[0][v], g_rowptr[0][v + 1], t);
    float ab = gather_sum(g_H1B, g_col[1], g_rowptr[1][v], g_rowptr[1][v + 1], t);
    float hv = fmaxf(ai * g_norm[1][v] + b1i[t], 0.f)
             + fmaxf(ab * g_norm[3][v] + b1b[t], 0.f);
    g_H[v * 128 + t] = hv * g_norm[0][v];   // pre-scale by nout_i for layer 2
}

__global__ void k_spmm2(const float* __restrict__ b2, float* __restrict__ out) {
    int v = blockIdx.x, t = threadIdx.x;
    float acc = gather_sum(g_H1, g_col[0], g_rowptr[0][v], g_rowptr[0][v + 1], t);
    out[v * 128 + t] = acc * g_norm[1][v] + b2[t];
}

// ---------------- launch ----------------
extern "C" void kernel_launch(void* const* d_in, const int* in_sizes, int n_in,
                              void* d_out, int out_size) {
    (void)in_sizes; (void)n_in; (void)out_size;
    const float* x    = (const float*)d_in[0];
    const int*   si   = (const int*)d_in[1];
    const int*   di   = (const int*)d_in[2];
    const int*   sb   = (const int*)d_in[3];
    const int*   db   = (const int*)d_in[4];
    const float* W1i  = (const float*)d_in[5];
    const float* b1i  = (const float*)d_in[6];
    const float* W1b  = (const float*)d_in[7];
    const float* b1b  = (const float*)d_in[8];
    const float* W2   = (const float*)d_in[9];
    const float* b2   = (const float*)d_in[10];
    float* out = (float*)d_out;

    k_zero<<<(6 * NN + 255) / 256, 256>>>();
    k_hist<<<(EE + 255) / 256, 256>>>(si, di, sb, db);
    k_norm<<<(NN + 255) / 256, 256>>>();
    {
        dim3 ga(NCH, 2);
        k_scanA<<<ga, 256>>>();
        k_scanB<<<2, 128>>>();
        k_scanC<<<ga, CHUNK>>>();
    }
    k_csrfill<<<(EE + 255) / 256, 256>>>(si, di, sb, db);

    const int gblk = (NN + 63) / 64;
    k_gemm<0><<<gblk, 512>>>(x, W1i, W1b);        // H1=(x@W1_i)*nout_i, H1B=(x@W1_b)*nout_b
    k_spmm1<<<NN, 128>>>(b1i, b1b);               // g_H = conv1 output * nout_i
    k_gemm<1><<<gblk, 512>>>(nullptr, W2, nullptr); // g_H1 = g_H @ W2
    k_spmm2<<<NN, 128>>>(b2, out);
}

// round 3
// speedup vs baseline: 1.2070x; 1.2070x over previous
#include <cuda_runtime.h>
#include <cstdint>

#define NN 100000
#define EE 1600000
#define FD 128
#define CHUNK 1024
#define NCH ((NN + CHUNK - 1) / CHUNK)   // 98

// ---------------- device scratch (static, no allocation) ----------------
__device__ int      g_cnt[4][NN];          // 0: out_i, 1: in_i, 2: out_b, 3: in_b
__device__ float    g_norm[4][NN];         // rsqrt(max(cnt,1))
__device__ int      g_rowptr[2][NN + 1];   // CSR by dst: 0=interacts, 1=behave
__device__ int      g_fill[2][NN];
__device__ int      g_col[2][EE];          // src indices per CSR slot
__device__ int      g_csums[2][NCH];
__device__ float    g_H1[NN * FD];         // (x@W1_i)*nout_i ; reused for H@W2 in layer 2
__device__ float    g_H1B[NN * FD];        // (x@W1_b)*nout_b
__device__ float    g_H[NN * FD];          // conv1 output, pre-scaled by nout_i
// W packed into mma.sync m16n8k8 tf32 B-fragment order, tf32-split:
// [0/1]: W1i hi/lo, [2/3]: W1b hi/lo, [4/5]: W2 hi/lo. 16384 u32 each.
__device__ uint32_t g_Wp[6][FD * FD];

// ---------------- helpers ----------------
__device__ __forceinline__ uint32_t cvt_tf32(float x) {
    uint32_t r;
    asm("cvt.rna.tf32.f32 %0, %1;" : "=r"(r) : "f"(x));
    return r;
}

__device__ __forceinline__ void mma8(float* c, const uint32_t* a, uint32_t b0, uint32_t b1) {
    asm volatile(
        "mma.sync.aligned.m16n8k8.row.col.f32.tf32.tf32.f32 "
        "{%0,%1,%2,%3}, {%4,%5,%6,%7}, {%8,%9}, {%0,%1,%2,%3};"
        : "+f"(c[0]), "+f"(c[1]), "+f"(c[2]), "+f"(c[3])
        : "r"(a[0]), "r"(a[1]), "r"(a[2]), "r"(a[3]), "r"(b0), "r"(b1));
}

// ---------------- prep kernels ----------------
__global__ void k_zero() {
    int i = blockIdx.x * blockDim.x + threadIdx.x;
    if (i < 4 * NN) ((int*)g_cnt)[i] = 0;
    else if (i < 6 * NN) ((int*)g_fill)[i - 4 * NN] = 0;
}

__global__ void k_hist(const int* __restrict__ si, const int* __restrict__ di,
                       const int* __restrict__ sb, const int* __restrict__ db) {
    int e = blockIdx.x * blockDim.x + threadIdx.x;
    if (e < EE) {
        atomicAdd(&g_cnt[0][si[e]], 1);
        atomicAdd(&g_cnt[1][di[e]], 1);
        atomicAdd(&g_cnt[2][sb[e]], 1);
        atomicAdd(&g_cnt[3][db[e]], 1);
    }
}

__global__ void k_norm() {
    int i = blockIdx.x * blockDim.x + threadIdx.x;
    if (i < NN) {
#pragma unroll
        for (int r = 0; r < 4; r++) {
            int c = g_cnt[r][i];
            if (c < 1) c = 1;
            g_norm[r][i] = rsqrtf((float)c);
        }
    }
}

// Pack W into per-lane fragment order + tf32 split.
// Fragment layout: idx = ((ks*16 + nt)*32 + lane)*2 + reg
//   value = W[k][n], k = ks*8 + (lane&3) + 4*reg, n = nt*8 + (lane>>2)
__global__ void k_prepW(const float* __restrict__ W1i, const float* __restrict__ W1b,
                        const float* __restrict__ W2) {
    int i = blockIdx.x * blockDim.x + threadIdx.x;
    if (i >= 3 * FD * FD) return;
    int m = i >> 14;
    int idx = i & 16383;
    int frag = idx >> 6;            // ks*16 + nt
    int ks = frag >> 4, nt = frag & 15;
    int lane = (idx >> 1) & 31;
    int reg = idx & 1;
    int k = ks * 8 + (lane & 3) + 4 * reg;
    int n = nt * 8 + (lane >> 2);
    const float* W = (m == 0) ? W1i : (m == 1) ? W1b : W2;
    float v = W[k * FD + n];
    uint32_t hi = cvt_tf32(v);
    uint32_t lo = cvt_tf32(v - __uint_as_float(hi));
    g_Wp[2 * m][idx] = hi;
    g_Wp[2 * m + 1][idx] = lo;
}

__global__ void k_scanA() {
    int rel = blockIdx.y;
    const int* cnt = g_cnt[1 + 2 * rel];
    int base = blockIdx.x * CHUNK;
    int sum = 0;
    for (int i = threadIdx.x; i < CHUNK; i += 256) {
        int gi = base + i;
        sum += (gi < NN) ? cnt[gi] : 0;
    }
    __shared__ int sh[8];
    for (int o = 16; o; o >>= 1) sum += __shfl_down_sync(0xFFFFFFFFu, sum, o);
    if ((threadIdx.x & 31) == 0) sh[threadIdx.x >> 5] = sum;
    __syncthreads();
    if (threadIdx.x == 0) {
        int s = 0;
        for (int w = 0; w < 8; w++) s += sh[w];
        g_csums[rel][blockIdx.x] = s;
    }
}

__global__ void k_scanB() {
    int rel = blockIdx.x;
    __shared__ int sh[NCH];
    if (threadIdx.x < NCH) sh[threadIdx.x] = g_csums[rel][threadIdx.x];
    __syncthreads();
    if (threadIdx.x == 0) {
        int acc = 0;
        for (int i = 0; i < NCH; i++) { int v = sh[i]; sh[i] = acc; acc += v; }
    }
    __syncthreads();
    if (threadIdx.x < NCH) g_csums[rel][threadIdx.x] = sh[threadIdx.x];
}

__global__ void k_scanC() {
    int rel = blockIdx.y;
    const int* cnt = g_cnt[1 + 2 * rel];
    int* rp = g_rowptr[rel];
    int gi = blockIdx.x * CHUNK + threadIdx.x;
    int v = (gi < NN) ? cnt[gi] : 0;
    __shared__ int sh[CHUNK];
    sh[threadIdx.x] = v;
    __syncthreads();
    int val = v;
    for (int off = 1; off < CHUNK; off <<= 1) {
        int t2 = (threadIdx.x >= off) ? sh[threadIdx.x - off] : 0;
        __syncthreads();
        val += t2;
        sh[threadIdx.x] = val;
        __syncthreads();
    }
    int offc = g_csums[rel][blockIdx.x];
    if (gi < NN) rp[gi] = offc + val - v;
    if (gi == NN - 1) rp[NN] = offc + val;
}

__global__ void k_csrfill(const int* __restrict__ si, const int* __restrict__ di,
                          const int* __restrict__ sb, const int* __restrict__ db) {
    int e = blockIdx.x * blockDim.x + threadIdx.x;
    if (e < EE) {
        int d = di[e];
        int p = g_rowptr[0][d] + atomicAdd(&g_fill[0][d], 1);
        g_col[0][p] = si[e];
        d = db[e];
        p = g_rowptr[1][d] + atomicAdd(&g_fill[1][d], 1);
        g_col[1][p] = sb[e];
    }
}

// ---------------- mma.sync tf32 GEMM ----------------
// Y[NN,128] = X[NN,128] @ W[128,128], 3xTF32 (hh + hl + lh).
// One CTA = 128x128 tile, 8 warps: warp w -> rows w*16..w*16+15, all 128 cols.
// MODE 0: X = x param, blockIdx.y selects W1i->g_H1*nout_i or W1b->g_H1B*nout_b.
// MODE 1: X = g_H, W2 -> g_H1, no scale.
#define XS_STRIDE 132

template <int MODE>
__global__ __launch_bounds__(256, 2) void k_gemm_mma(const float* __restrict__ Xext) {
    extern __shared__ float xs[];   // [128][XS_STRIDE]
    const float* __restrict__ X = (MODE == 0) ? Xext : g_H;
    const int t = threadIdx.x, wid = t >> 5, lane = t & 31;
    const int bm = blockIdx.x * 128;

    // stage X tile (zero-padded)
    for (int i = t; i < 128 * 32; i += 256) {
        int r = i >> 5, c4 = (i & 31) * 4;
        float4 v = make_float4(0.f, 0.f, 0.f, 0.f);
        if (bm + r < NN) v = *(const float4*)(X + (size_t)(bm + r) * FD + c4);
        *(float4*)&xs[r * XS_STRIDE + c4] = v;
    }
    __syncthreads();

    const uint32_t* __restrict__ Wh = g_Wp[(MODE == 0) ? 2 * blockIdx.y : 4];
    const uint32_t* __restrict__ Wl = g_Wp[(MODE == 0) ? 2 * blockIdx.y + 1 : 5];

    float acc[16][4];
#pragma unroll
    for (int nt = 0; nt < 16; nt++)
#pragma unroll
        for (int j = 0; j < 4; j++) acc[nt][j] = 0.f;

    const int r0 = wid * 16 + (lane >> 2);   // local row of a0/a2
    const int c0 = lane & 3;

#pragma unroll 4
    for (int ks = 0; ks < 16; ks++) {
        const int k0 = ks * 8;
        float x00 = xs[r0 * XS_STRIDE + k0 + c0];
        float x10 = xs[(r0 + 8) * XS_STRIDE + k0 + c0];
        float x01 = xs[r0 * XS_STRIDE + k0 + c0 + 4];
        float x11 = xs[(r0 + 8) * XS_STRIDE + k0 + c0 + 4];
        uint32_t ah[4], al[4];
        ah[0] = cvt_tf32(x00); al[0] = cvt_tf32(x00 - __uint_as_float(ah[0]));
        ah[1] = cvt_tf32(x10); al[1] = cvt_tf32(x10 - __uint_as_float(ah[1]));
        ah[2] = cvt_tf32(x01); al[2] = cvt_tf32(x01 - __uint_as_float(ah[2]));
        ah[3] = cvt_tf32(x11); al[3] = cvt_tf32(x11 - __uint_as_float(ah[3]));

        const uint2* wh = (const uint2*)(Wh + ks * 16 * 64) + lane;
        const uint2* wl = (const uint2*)(Wl + ks * 16 * 64) + lane;
#pragma unroll
        for (int nt = 0; nt < 16; nt++) {
            uint2 bh = wh[nt * 32];
            uint2 bl = wl[nt * 32];
            mma8(acc[nt], ah, bh.x, bh.y);
            mma8(acc[nt], ah, bl.x, bl.y);
            mma8(acc[nt], al, bh.x, bh.y);
        }
    }

    // epilogue
    const int m0 = bm + r0;
    const int m1 = m0 + 8;
    float s0 = 1.f, s1 = 1.f;
    float* O = g_H1;
    if (MODE == 0) {
        int which = blockIdx.y ? 2 : 0;
        if (m0 < NN) s0 = g_norm[which][m0];
        if (m1 < NN) s1 = g_norm[which][m1];
        if (blockIdx.y) O = g_H1B;
    }
#pragma unroll
    for (int nt = 0; nt < 16; nt++) {
        int col = nt * 8 + 2 * (lane & 3);
        if (m0 < NN) {
            float2 o = make_float2(acc[nt][0] * s0, acc[nt][1] * s0);
            *(float2*)&O[(size_t)m0 * FD + col] = o;
        }
        if (m1 < NN) {
            float2 o = make_float2(acc[nt][2] * s1, acc[nt][3] * s1);
            *(float2*)&O[(size_t)m1 * FD + col] = o;
        }
    }
}

// ---------------- SpMM: one block (128 threads) per node, thread = feature ----------------
__device__ __forceinline__ float gather_sum(const float* __restrict__ Hbuf,
                                            const int* __restrict__ col,
                                            int e, int e1, int t) {
    float acc = 0.f;
    for (; e + 4 <= e1; e += 4) {
        int s0 = col[e], s1 = col[e + 1], s2 = col[e + 2], s3 = col[e + 3];
        float v0 = Hbuf[s0 * 128 + t];
        float v1 = Hbuf[s1 * 128 + t];
        float v2 = Hbuf[s2 * 128 + t];
        float v3 = Hbuf[s3 * 128 + t];
        acc += (v0 + v1) + (v2 + v3);
    }
    for (; e < e1; e++) acc += Hbuf[col[e] * 128 + t];
    return acc;
}

__global__ void k_spmm1(const float* __restrict__ b1i, const float* __restrict__ b1b) {
    int v = blockIdx.x, t = threadIdx.x;
    float ai = gather_sum(g_H1,  g_col[0], g_rowptr[0][v], g_rowptr[0][v + 1], t);
    float ab = gather_sum(g_H1B, g_col[1], g_rowptr[1][v], g_rowptr[1][v + 1], t);
    float hv = fmaxf(ai * g_norm[1][v] + b1i[t], 0.f)
             + fmaxf(ab * g_norm[3][v] + b1b[t], 0.f);
    g_H[v * 128 + t] = hv * g_norm[0][v];   // pre-scale by nout_i for layer 2
}

__global__ void k_spmm2(const float* __restrict__ b2, float* __restrict__ out) {
    int v = blockIdx.x, t = threadIdx.x;
    float acc = gather_sum(g_H1, g_col[0], g_rowptr[0][v], g_rowptr[0][v + 1], t);
    out[v * 128 + t] = acc * g_norm[1][v] + b2[t];
}

// ---------------- launch ----------------
extern "C" void kernel_launch(void* const* d_in, const int* in_sizes, int n_in,
                              void* d_out, int out_size) {
    (void)in_sizes; (void)n_in; (void)out_size;
    const float* x    = (const float*)d_in[0];
    const int*   si   = (const int*)d_in[1];
    const int*   di   = (const int*)d_in[2];
    const int*   sb   = (const int*)d_in[3];
    const int*   db   = (const int*)d_in[4];
    const float* W1i  = (const float*)d_in[5];
    const float* b1i  = (const float*)d_in[6];
    const float* W1b  = (const float*)d_in[7];
    const float* b1b  = (const float*)d_in[8];
    const float* W2   = (const float*)d_in[9];
    const float* b2   = (const float*)d_in[10];
    float* out = (float*)d_out;

    const int XS_BYTES = 128 * XS_STRIDE * sizeof(float);   // 67584
    static int attr_done = 0;
    if (!attr_done) {
        cudaFuncSetAttribute(k_gemm_mma<0>, cudaFuncAttributeMaxDynamicSharedMemorySize, XS_BYTES);
        cudaFuncSetAttribute(k_gemm_mma<1>, cudaFuncAttributeMaxDynamicSharedMemorySize, XS_BYTES);
        attr_done = 1;
    }

    k_zero<<<(6 * NN + 255) / 256, 256>>>();
    k_hist<<<(EE + 255) / 256, 256>>>(si, di, sb, db);
    k_prepW<<<(3 * FD * FD + 255) / 256, 256>>>(W1i, W1b, W2);
    k_norm<<<(NN + 255) / 256, 256>>>();
    {
        dim3 ga(NCH, 2);
        k_scanA<<<ga, 256>>>();
        k_scanB<<<2, 128>>>();
        k_scanC<<<ga, CHUNK>>>();
    }
    k_csrfill<<<(EE + 255) / 256, 256>>>(si, di, sb, db);

    const int gblk = (NN + 127) / 128;   // 782
    k_gemm_mma<0><<<dim3(gblk, 2), 256, XS_BYTES>>>(x);   // g_H1, g_H1B
    k_spmm1<<<NN, 128>>>(b1i, b1b);                       // g_H
    k_gemm_mma<1><<<dim3(gblk, 1), 256, XS_BYTES>>>(nullptr); // g_H1 = g_H @ W2
    k_spmm2<<<NN, 128>>>(b2, out);
}

// round 4
// speedup vs baseline: 1.5584x; 1.2911x over previous
#include <cuda_runtime.h>
#include <cuda_fp16.h>
#include <cstdint>

#define NN 100000
#define EE 1600000
#define FD 128
#define CHUNK 1024
#define NCH ((NN + CHUNK - 1) / CHUNK)   // 98

// ---------------- device scratch (static, no allocation) ----------------
__device__ int      g_cnt[4][NN];          // 0: out_i, 1: in_i, 2: out_b, 3: in_b
__device__ float    g_norm[4][NN];         // rsqrt(max(cnt,1))
__device__ int      g_rowptr[2][NN + 1];   // CSR by dst: 0=interacts, 1=behave
__device__ int      g_fill[2][NN];
__device__ int      g_col[2][EE];          // src indices per CSR slot
__device__ int      g_csums[2][NCH];
__device__ __half2  g_H1h[NN * 64];        // (x@W1_i)*nout_i  (fp16, gathered); reused for H@W2
__device__ __half2  g_H1Bh[NN * 64];       // (x@W1_b)*nout_b  (fp16, gathered)
__device__ float    g_H[NN * FD];          // conv1 output fp32, pre-scaled by nout_i
// W packed into mma.sync m16n8k8 tf32 B-fragment order, tf32-split:
// [0/1]: W1i hi/lo, [2/3]: W1b hi/lo, [4/5]: W2 hi/lo. 16384 u32 each.
__device__ uint32_t g_Wp[6][FD * FD];

// ---------------- helpers ----------------
__device__ __forceinline__ uint32_t cvt_tf32(float x) {
    uint32_t r;
    asm("cvt.rna.tf32.f32 %0, %1;" : "=r"(r) : "f"(x));
    return r;
}

__device__ __forceinline__ void mma8(float* c, const uint32_t* a, uint32_t b0, uint32_t b1) {
    asm volatile(
        "mma.sync.aligned.m16n8k8.row.col.f32.tf32.tf32.f32 "
        "{%0,%1,%2,%3}, {%4,%5,%6,%7}, {%8,%9}, {%0,%1,%2,%3};"
        : "+f"(c[0]), "+f"(c[1]), "+f"(c[2]), "+f"(c[3])
        : "r"(a[0]), "r"(a[1]), "r"(a[2]), "r"(a[3]), "r"(b0), "r"(b1));
}

// ---------------- prep kernels ----------------
__global__ void k_zero() {
    int i = blockIdx.x * blockDim.x + threadIdx.x;
    if (i < 4 * NN) ((int*)g_cnt)[i] = 0;
    else if (i < 6 * NN) ((int*)g_fill)[i - 4 * NN] = 0;
}

__global__ void k_hist(const int* __restrict__ si, const int* __restrict__ di,
                       const int* __restrict__ sb, const int* __restrict__ db) {
    int e = blockIdx.x * blockDim.x + threadIdx.x;
    if (e < EE) {
        atomicAdd(&g_cnt[0][si[e]], 1);
        atomicAdd(&g_cnt[1][di[e]], 1);
        atomicAdd(&g_cnt[2][sb[e]], 1);
        atomicAdd(&g_cnt[3][db[e]], 1);
    }
}

__global__ void k_norm() {
    int i = blockIdx.x * blockDim.x + threadIdx.x;
    if (i < NN) {
#pragma unroll
        for (int r = 0; r < 4; r++) {
            int c = g_cnt[r][i];
            if (c < 1) c = 1;
            g_norm[r][i] = rsqrtf((float)c);
        }
    }
}

// Pack W into per-lane fragment order + tf32 split.
// Fragment layout: idx = ((ks*16 + nt)*32 + lane)*2 + reg
//   value = W[k][n], k = ks*8 + (lane&3) + 4*reg, n = nt*8 + (lane>>2)
__global__ void k_prepW(const float* __restrict__ W1i, const float* __restrict__ W1b,
                        const float* __restrict__ W2) {
    int i = blockIdx.x * blockDim.x + threadIdx.x;
    if (i >= 3 * FD * FD) return;
    int m = i >> 14;
    int idx = i & 16383;
    int frag = idx >> 6;            // ks*16 + nt
    int ks = frag >> 4, nt = frag & 15;
    int lane = (idx >> 1) & 31;
    int reg = idx & 1;
    int k = ks * 8 + (lane & 3) + 4 * reg;
    int n = nt * 8 + (lane >> 2);
    const float* W = (m == 0) ? W1i : (m == 1) ? W1b : W2;
    float v = W[k * FD + n];
    uint32_t hi = cvt_tf32(v);
    uint32_t lo = cvt_tf32(v - __uint_as_float(hi));
    g_Wp[2 * m][idx] = hi;
    g_Wp[2 * m + 1][idx] = lo;
}

__global__ void k_scanA() {
    int rel = blockIdx.y;
    const int* cnt = g_cnt[1 + 2 * rel];
    int base = blockIdx.x * CHUNK;
    int sum = 0;
    for (int i = threadIdx.x; i < CHUNK; i += 256) {
        int gi = base + i;
        sum += (gi < NN) ? cnt[gi] : 0;
    }
    __shared__ int sh[8];
    for (int o = 16; o; o >>= 1) sum += __shfl_down_sync(0xFFFFFFFFu, sum, o);
    if ((threadIdx.x & 31) == 0) sh[threadIdx.x >> 5] = sum;
    __syncthreads();
    if (threadIdx.x == 0) {
        int s = 0;
        for (int w = 0; w < 8; w++) s += sh[w];
        g_csums[rel][blockIdx.x] = s;
    }
}

__global__ void k_scanB() {
    int rel = blockIdx.x;
    __shared__ int sh[NCH];
    if (threadIdx.x < NCH) sh[threadIdx.x] = g_csums[rel][threadIdx.x];
    __syncthreads();
    if (threadIdx.x == 0) {
        int acc = 0;
        for (int i = 0; i < NCH; i++) { int v = sh[i]; sh[i] = acc; acc += v; }
    }
    __syncthreads();
    if (threadIdx.x < NCH) g_csums[rel][threadIdx.x] = sh[threadIdx.x];
}

__global__ void k_scanC() {
    int rel = blockIdx.y;
    const int* cnt = g_cnt[1 + 2 * rel];
    int* rp = g_rowptr[rel];
    int gi = blockIdx.x * CHUNK + threadIdx.x;
    int v = (gi < NN) ? cnt[gi] : 0;
    __shared__ int sh[CHUNK];
    sh[threadIdx.x] = v;
    __syncthreads();
    int val = v;
    for (int off = 1; off < CHUNK; off <<= 1) {
        int t2 = (threadIdx.x >= off) ? sh[threadIdx.x - off] : 0;
        __syncthreads();
        val += t2;
        sh[threadIdx.x] = val;
        __syncthreads();
    }
    int offc = g_csums[rel][blockIdx.x];
    if (gi < NN) rp[gi] = offc + val - v;
    if (gi == NN - 1) rp[NN] = offc + val;
}

__global__ void k_csrfill(const int* __restrict__ si, const int* __restrict__ di,
                          const int* __restrict__ sb, const int* __restrict__ db) {
    int e = blockIdx.x * blockDim.x + threadIdx.x;
    if (e < EE) {
        int d = di[e];
        int p = g_rowptr[0][d] + atomicAdd(&g_fill[0][d], 1);
        g_col[0][p] = si[e];
        d = db[e];
        p = g_rowptr[1][d] + atomicAdd(&g_fill[1][d], 1);
        g_col[1][p] = sb[e];
    }
}

// ---------------- mma.sync tf32 GEMM ----------------
// Y[NN,128] = X[NN,128] @ W[128,128], 3xTF32 (hh + hl + lh), fp16 packed output.
// One CTA = 128x128 tile, 8 warps: warp w -> rows w*16..w*16+15, all 128 cols.
// MODE 0: X = x param, blockIdx.y selects W1i->g_H1h*nout_i or W1b->g_H1Bh*nout_b.
// MODE 1: X = g_H, W2 -> g_H1h, no scale.
#define XS_STRIDE 132

template <int MODE>
__global__ __launch_bounds__(256, 2) void k_gemm_mma(const float* __restrict__ Xext) {
    extern __shared__ float xs[];   // [128][XS_STRIDE]
    const float* __restrict__ X = (MODE == 0) ? Xext : g_H;
    const int t = threadIdx.x, wid = t >> 5, lane = t & 31;
    const int bm = blockIdx.x * 128;

    // stage X tile (zero-padded)
    for (int i = t; i < 128 * 32; i += 256) {
        int r = i >> 5, c4 = (i & 31) * 4;
        float4 v = make_float4(0.f, 0.f, 0.f, 0.f);
        if (bm + r < NN) v = *(const float4*)(X + (size_t)(bm + r) * FD + c4);
        *(float4*)&xs[r * XS_STRIDE + c4] = v;
    }
    __syncthreads();

    const uint32_t* __restrict__ Wh = g_Wp[(MODE == 0) ? 2 * blockIdx.y : 4];
    const uint32_t* __restrict__ Wl = g_Wp[(MODE == 0) ? 2 * blockIdx.y + 1 : 5];

    float acc[16][4];
#pragma unroll
    for (int nt = 0; nt < 16; nt++)
#pragma unroll
        for (int j = 0; j < 4; j++) acc[nt][j] = 0.f;

    const int r0 = wid * 16 + (lane >> 2);   // local row of a0/a2
    const int c0 = lane & 3;

#pragma unroll 4
    for (int ks = 0; ks < 16; ks++) {
        const int k0 = ks * 8;
        float x00 = xs[r0 * XS_STRIDE + k0 + c0];
        float x10 = xs[(r0 + 8) * XS_STRIDE + k0 + c0];
        float x01 = xs[r0 * XS_STRIDE + k0 + c0 + 4];
        float x11 = xs[(r0 + 8) * XS_STRIDE + k0 + c0 + 4];
        uint32_t ah[4], al[4];
        ah[0] = cvt_tf32(x00); al[0] = cvt_tf32(x00 - __uint_as_float(ah[0]));
        ah[1] = cvt_tf32(x10); al[1] = cvt_tf32(x10 - __uint_as_float(ah[1]));
        ah[2] = cvt_tf32(x01); al[2] = cvt_tf32(x01 - __uint_as_float(ah[2]));
        ah[3] = cvt_tf32(x11); al[3] = cvt_tf32(x11 - __uint_as_float(ah[3]));

        const uint2* wh = (const uint2*)(Wh + ks * 16 * 64) + lane;
        const uint2* wl = (const uint2*)(Wl + ks * 16 * 64) + lane;
#pragma unroll
        for (int nt = 0; nt < 16; nt++) {
            uint2 bh = wh[nt * 32];
            uint2 bl = wl[nt * 32];
            mma8(acc[nt], ah, bh.x, bh.y);
            mma8(acc[nt], ah, bl.x, bl.y);
            mma8(acc[nt], al, bh.x, bh.y);
        }
    }

    // epilogue: pack to half2
    const int m0 = bm + r0;
    const int m1 = m0 + 8;
    float s0 = 1.f, s1 = 1.f;
    __half2* O = g_H1h;
    if (MODE == 0) {
        int which = blockIdx.y ? 2 : 0;
        if (m0 < NN) s0 = g_norm[which][m0];
        if (m1 < NN) s1 = g_norm[which][m1];
        if (blockIdx.y) O = g_H1Bh;
    }
    const int hc = lane & 3;   // half2 col offset within n-tile
#pragma unroll
    for (int nt = 0; nt < 16; nt++) {
        int hcol = nt * 4 + hc;
        if (m0 < NN) O[(size_t)m0 * 64 + hcol] = __floats2half2_rn(acc[nt][0] * s0, acc[nt][1] * s0);
        if (m1 < NN) O[(size_t)m1 * 64 + hcol] = __floats2half2_rn(acc[nt][2] * s1, acc[nt][3] * s1);
    }
}

// ---------------- SpMM: 64 lanes (half2 features) x 4 nodes per block ----------------
__device__ __forceinline__ float2 gather_h(const __half2* __restrict__ H,
                                           const int* __restrict__ col,
                                           int e, int e1, int lane) {
    float a0 = 0.f, a1 = 0.f;
    for (; e + 4 <= e1; e += 4) {
        int s0 = col[e], s1 = col[e + 1], s2 = col[e + 2], s3 = col[e + 3];
        float2 f0 = __half22float2(H[(size_t)s0 * 64 + lane]);
        float2 f1 = __half22float2(H[(size_t)s1 * 64 + lane]);
        float2 f2 = __half22float2(H[(size_t)s2 * 64 + lane]);
        float2 f3 = __half22float2(H[(size_t)s3 * 64 + lane]);
        a0 += (f0.x + f1.x) + (f2.x + f3.x);
        a1 += (f0.y + f1.y) + (f2.y + f3.y);
    }
    for (; e < e1; e++) {
        float2 f = __half22float2(H[(size_t)col[e] * 64 + lane]);
        a0 += f.x;
        a1 += f.y;
    }
    return make_float2(a0, a1);
}

__global__ void k_spmm1(const float* __restrict__ b1i, const float* __restrict__ b1b) {
    int v = blockIdx.x * 4 + threadIdx.y;
    if (v >= NN) return;
    int lane = threadIdx.x;
    float2 ai = gather_h(g_H1h,  g_col[0], g_rowptr[0][v], g_rowptr[0][v + 1], lane);
    float2 ab = gather_h(g_H1Bh, g_col[1], g_rowptr[1][v], g_rowptr[1][v + 1], lane);
    float n1 = g_norm[1][v], n3 = g_norm[3][v], n0 = g_norm[0][v];
    float h0 = fmaxf(ai.x * n1 + b1i[2 * lane], 0.f) + fmaxf(ab.x * n3 + b1b[2 * lane], 0.f);
    float h1 = fmaxf(ai.y * n1 + b1i[2 * lane + 1], 0.f) + fmaxf(ab.y * n3 + b1b[2 * lane + 1], 0.f);
    *(float2*)&g_H[(size_t)v * 128 + 2 * lane] = make_float2(h0 * n0, h1 * n0);
}

__global__ void k_spmm2(const float* __restrict__ b2, float* __restrict__ out) {
    int v = blockIdx.x * 4 + threadIdx.y;
    if (v >= NN) return;
    int lane = threadIdx.x;
    float2 a = gather_h(g_H1h, g_col[0], g_rowptr[0][v], g_rowptr[0][v + 1], lane);
    float n1 = g_norm[1][v];
    *(float2*)&out[(size_t)v * 128 + 2 * lane] =
        make_float2(a.x * n1 + b2[2 * lane], a.y * n1 + b2[2 * lane + 1]);
}

// ---------------- launch ----------------
extern "C" void kernel_launch(void* const* d_in, const int* in_sizes, int n_in,
                              void* d_out, int out_size) {
    (void)in_sizes; (void)n_in; (void)out_size;
    const float* x    = (const float*)d_in[0];
    const int*   si   = (const int*)d_in[1];
    const int*   di   = (const int*)d_in[2];
    const int*   sb   = (const int*)d_in[3];
    const int*   db   = (const int*)d_in[4];
    const float* W1i  = (const float*)d_in[5];
    const float* b1i  = (const float*)d_in[6];
    const float* W1b  = (const float*)d_in[7];
    const float* b1b  = (const float*)d_in[8];
    const float* W2   = (const float*)d_in[9];
    const float* b2   = (const float*)d_in[10];
    float* out = (float*)d_out;

    const int XS_BYTES = 128 * XS_STRIDE * sizeof(float);   // 67584
    static int attr_done = 0;
    if (!attr_done) {
        cudaFuncSetAttribute(k_gemm_mma<0>, cudaFuncAttributeMaxDynamicSharedMemorySize, XS_BYTES);
        cudaFuncSetAttribute(k_gemm_mma<1>, cudaFuncAttributeMaxDynamicSharedMemorySize, XS_BYTES);
        attr_done = 1;
    }

    k_zero<<<(6 * NN + 255) / 256, 256>>>();
    k_hist<<<(EE + 255) / 256, 256>>>(si, di, sb, db);
    k_prepW<<<(3 * FD * FD + 255) / 256, 256>>>(W1i, W1b, W2);
    k_norm<<<(NN + 255) / 256, 256>>>();
    {
        dim3 ga(NCH, 2);
        k_scanA<<<ga, 256>>>();
        k_scanB<<<2, 128>>>();
        k_scanC<<<ga, CHUNK>>>();
    }
    k_csrfill<<<(EE + 255) / 256, 256>>>(si, di, sb, db);

    const int gblk = (NN + 127) / 128;   // 782
    const dim3 sblk(64, 4);
    const int sgrid = (NN + 3) / 4;      // 25000

    k_gemm_mma<0><<<dim3(gblk, 2), 256, XS_BYTES>>>(x);       // g_H1h, g_H1Bh
    k_spmm1<<<sgrid, sblk>>>(b1i, b1b);                       // g_H (fp32)
    k_gemm_mma<1><<<dim3(gblk, 1), 256, XS_BYTES>>>(nullptr); // g_H1h = g_H @ W2
    k_spmm2<<<sgrid, sblk>>>(b2, out);
}

// round 5
// speedup vs baseline: 1.7901x; 1.1487x over previous
#include <cuda_runtime.h>
#include <cuda_fp16.h>
#include <cstdint>

#define NN 100000
#define EE 1600000
#define FD 128
#define CHUNK 1024
#define NCH ((NN + CHUNK - 1) / CHUNK)   // 98

// ---------------- device scratch (static, no allocation) ----------------
__device__ int      g_cnt[4][NN];          // 0: out_i, 1: in_i, 2: out_b, 3: in_b
__device__ float    g_norm[4][NN];         // rsqrt(max(cnt,1))
__device__ int      g_rowptr[2][NN + 1];   // CSR by dst: 0=interacts, 1=behave
__device__ int      g_fill[2][NN];
__device__ int      g_col[2][EE];          // src indices per CSR slot
__device__ int      g_csums[2][NCH];
__device__ __half2  g_H1h[NN * 64];        // (x@W1_i)*nout_i  (fp16, gathered); reused for H@W2
__device__ __half2  g_H1Bh[NN * 64];       // (x@W1_b)*nout_b  (fp16, gathered)
__device__ float    g_H[NN * FD];          // conv1 output fp32, pre-scaled by nout_i
// W packed into mma.sync m16n8k16 f16 B-fragment order (half2 words), fp16-split:
// [0/1]: W1i hi/lo, [2/3]: W1b hi/lo, [4/5]: W2 hi/lo. 8192 u32 each.
__device__ uint32_t g_Wp[6][FD * FD / 2];

// ---------------- helpers ----------------
__device__ __forceinline__ void mma16(float* c, const uint32_t* a, uint32_t b0, uint32_t b1) {
    asm volatile(
        "mma.sync.aligned.m16n8k16.row.col.f32.f16.f16.f32 "
        "{%0,%1,%2,%3}, {%4,%5,%6,%7}, {%8,%9}, {%0,%1,%2,%3};"
        : "+f"(c[0]), "+f"(c[1]), "+f"(c[2]), "+f"(c[3])
        : "r"(a[0]), "r"(a[1]), "r"(a[2]), "r"(a[3]), "r"(b0), "r"(b1));
}

__device__ __forceinline__ void split2(float vx, float vy, uint32_t& hi, uint32_t& lo) {
    __half hx = __float2half_rn(vx), hy = __float2half_rn(vy);
    __half lx = __float2half_rn(vx - __half2float(hx));
    __half ly = __float2half_rn(vy - __half2float(hy));
    __half2 h2 = __halves2half2(hx, hy);
    __half2 l2 = __halves2half2(lx, ly);
    hi = *reinterpret_cast<uint32_t*>(&h2);
    lo = *reinterpret_cast<uint32_t*>(&l2);
}

// ---------------- prep kernels ----------------
__global__ void k_zero() {
    int i = blockIdx.x * blockDim.x + threadIdx.x;
    if (i < 4 * NN) ((int*)g_cnt)[i] = 0;
    else if (i < 6 * NN) ((int*)g_fill)[i - 4 * NN] = 0;
}

__global__ void k_hist(const int* __restrict__ si, const int* __restrict__ di,
                       const int* __restrict__ sb, const int* __restrict__ db) {
    int e = blockIdx.x * blockDim.x + threadIdx.x;
    if (e < EE) {
        atomicAdd(&g_cnt[0][si[e]], 1);
        atomicAdd(&g_cnt[1][di[e]], 1);
        atomicAdd(&g_cnt[2][sb[e]], 1);
        atomicAdd(&g_cnt[3][db[e]], 1);
    }
}

__global__ void k_norm() {
    int i = blockIdx.x * blockDim.x + threadIdx.x;
    if (i < NN) {
#pragma unroll
        for (int r = 0; r < 4; r++) {
            int c = g_cnt[r][i];
            if (c < 1) c = 1;
            g_norm[r][i] = rsqrtf((float)c);
        }
    }
}

// Pack W into per-lane m16n8k16 f16 B-fragment order + fp16 split.
// Word layout: idx = (ks*16 + nt)*64 + lane*2 + reg
//   n = nt*8 + (lane>>2); k = ks*16 + (lane&3)*2 + reg*8; halves = {k, k+1}
__global__ void k_prepW(const float* __restrict__ W1i, const float* __restrict__ W1b,
                        const float* __restrict__ W2) {
    int i = blockIdx.x * blockDim.x + threadIdx.x;
    if (i >= 3 * 8192) return;
    int m = i / 8192;
    int idx = i & 8191;
    int frag = idx >> 6;            // ks*16 + nt
    int ks = frag >> 4, nt = frag & 15;
    int rem = idx & 63;
    int lane = rem >> 1, reg = rem & 1;
    int n = nt * 8 + (lane >> 2);
    int k = ks * 16 + (lane & 3) * 2 + reg * 8;
    const float* W = (m == 0) ? W1i : (m == 1) ? W1b : W2;
    float v0 = W[k * FD + n];
    float v1 = W[(k + 1) * FD + n];
    uint32_t hi, lo;
    split2(v0, v1, hi, lo);
    g_Wp[2 * m][idx] = hi;
    g_Wp[2 * m + 1][idx] = lo;
}

__global__ void k_scanA() {
    int rel = blockIdx.y;
    const int* cnt = g_cnt[1 + 2 * rel];
    int base = blockIdx.x * CHUNK;
    int sum = 0;
    for (int i = threadIdx.x; i < CHUNK; i += 256) {
        int gi = base + i;
        sum += (gi < NN) ? cnt[gi] : 0;
    }
    __shared__ int sh[8];
    for (int o = 16; o; o >>= 1) sum += __shfl_down_sync(0xFFFFFFFFu, sum, o);
    if ((threadIdx.x & 31) == 0) sh[threadIdx.x >> 5] = sum;
    __syncthreads();
    if (threadIdx.x == 0) {
        int s = 0;
        for (int w = 0; w < 8; w++) s += sh[w];
        g_csums[rel][blockIdx.x] = s;
    }
}

__global__ void k_scanB() {
    int rel = blockIdx.x;
    __shared__ int sh[NCH];
    if (threadIdx.x < NCH) sh[threadIdx.x] = g_csums[rel][threadIdx.x];
    __syncthreads();
    if (threadIdx.x == 0) {
        int acc = 0;
        for (int i = 0; i < NCH; i++) { int v = sh[i]; sh[i] = acc; acc += v; }
    }
    __syncthreads();
    if (threadIdx.x < NCH) g_csums[rel][threadIdx.x] = sh[threadIdx.x];
}

__global__ void k_scanC() {
    int rel = blockIdx.y;
    const int* cnt = g_cnt[1 + 2 * rel];
    int* rp = g_rowptr[rel];
    int gi = blockIdx.x * CHUNK + threadIdx.x;
    int v = (gi < NN) ? cnt[gi] : 0;
    __shared__ int sh[CHUNK];
    sh[threadIdx.x] = v;
    __syncthreads();
    int val = v;
    for (int off = 1; off < CHUNK; off <<= 1) {
        int t2 = (threadIdx.x >= off) ? sh[threadIdx.x - off] : 0;
        __syncthreads();
        val += t2;
        sh[threadIdx.x] = val;
        __syncthreads();
    }
    int offc = g_csums[rel][blockIdx.x];
    if (gi < NN) rp[gi] = offc + val - v;
    if (gi == NN - 1) rp[NN] = offc + val;
}

__global__ void k_csrfill(const int* __restrict__ si, const int* __restrict__ di,
                          const int* __restrict__ sb, const int* __restrict__ db) {
    int e = blockIdx.x * blockDim.x + threadIdx.x;
    if (e < EE) {
        int d = di[e];
        int p = g_rowptr[0][d] + atomicAdd(&g_fill[0][d], 1);
        g_col[0][p] = si[e];
        d = db[e];
        p = g_rowptr[1][d] + atomicAdd(&g_fill[1][d], 1);
        g_col[1][p] = sb[e];
    }
}

// ---------------- split-fp16 mma GEMM ----------------
// Y[NN,128] = X[NN,128] @ W[128,128], split-fp16 (hh + hl + lh), fp16 packed output.
// One CTA = 128x128 tile, 8 warps: warp w -> rows w*16..w*16+15, all 128 cols.
// MODE 0: X = x param, blockIdx.y selects W1i->g_H1h*nout_i or W1b->g_H1Bh*nout_b.
// MODE 1: X = g_H, W2 -> g_H1h, no scale.
#define XS_STRIDE 132

template <int MODE>
__global__ __launch_bounds__(256, 2) void k_gemm_mma(const float* __restrict__ Xext) {
    extern __shared__ float xs[];   // [128][XS_STRIDE]
    const float* __restrict__ X = (MODE == 0) ? Xext : g_H;
    const int t = threadIdx.x, wid = t >> 5, lane = t & 31;
    const int bm = blockIdx.x * 128;

    // stage X tile (zero-padded)
    for (int i = t; i < 128 * 32; i += 256) {
        int r = i >> 5, c4 = (i & 31) * 4;
        float4 v = make_float4(0.f, 0.f, 0.f, 0.f);
        if (bm + r < NN) v = *(const float4*)(X + (size_t)(bm + r) * FD + c4);
        *(float4*)&xs[r * XS_STRIDE + c4] = v;
    }
    __syncthreads();

    const uint32_t* __restrict__ Wh = g_Wp[(MODE == 0) ? 2 * blockIdx.y : 4];
    const uint32_t* __restrict__ Wl = g_Wp[(MODE == 0) ? 2 * blockIdx.y + 1 : 5];

    float acc[16][4];
#pragma unroll
    for (int nt = 0; nt < 16; nt++)
#pragma unroll
        for (int j = 0; j < 4; j++) acc[nt][j] = 0.f;

    const int r0 = wid * 16 + (lane >> 2);   // local row of a0/a2
    const int c0 = (lane & 3) * 2;

#pragma unroll
    for (int ks = 0; ks < 8; ks++) {
        const int k0 = ks * 16;
        float2 v00 = *(const float2*)&xs[r0 * XS_STRIDE + k0 + c0];
        float2 v10 = *(const float2*)&xs[(r0 + 8) * XS_STRIDE + k0 + c0];
        float2 v01 = *(const float2*)&xs[r0 * XS_STRIDE + k0 + 8 + c0];
        float2 v11 = *(const float2*)&xs[(r0 + 8) * XS_STRIDE + k0 + 8 + c0];
        uint32_t ah[4], al[4];
        split2(v00.x, v00.y, ah[0], al[0]);
        split2(v10.x, v10.y, ah[1], al[1]);
        split2(v01.x, v01.y, ah[2], al[2]);
        split2(v11.x, v11.y, ah[3], al[3]);

        const uint2* wh = (const uint2*)(Wh + ks * 1024) + lane;
        const uint2* wl = (const uint2*)(Wl + ks * 1024) + lane;
#pragma unroll
        for (int nt = 0; nt < 16; nt++) {
            uint2 bh = wh[nt * 32];
            uint2 bl = wl[nt * 32];
            mma16(acc[nt], ah, bh.x, bh.y);   // hh
            mma16(acc[nt], al, bh.x, bh.y);   // lh
            mma16(acc[nt], ah, bl.x, bl.y);   // hl
        }
    }

    // epilogue: pack to half2
    const int m0 = bm + r0;
    const int m1 = m0 + 8;
    float s0 = 1.f, s1 = 1.f;
    __half2* O = g_H1h;
    if (MODE == 0) {
        int which = blockIdx.y ? 2 : 0;
        if (m0 < NN) s0 = g_norm[which][m0];
        if (m1 < NN) s1 = g_norm[which][m1];
        if (blockIdx.y) O = g_H1Bh;
    }
    const int hc = lane & 3;   // half2 col offset within n-tile
#pragma unroll
    for (int nt = 0; nt < 16; nt++) {
        int hcol = nt * 4 + hc;
        if (m0 < NN) O[(size_t)m0 * 64 + hcol] = __floats2half2_rn(acc[nt][0] * s0, acc[nt][1] * s0);
        if (m1 < NN) O[(size_t)m1 * 64 + hcol] = __floats2half2_rn(acc[nt][2] * s1, acc[nt][3] * s1);
    }
}

// ---------------- SpMM: 64 lanes (half2 features) x 4 nodes per block ----------------
__device__ __forceinline__ float2 gather_h(const __half2* __restrict__ H,
                                           const int* __restrict__ col,
                                           int e, int e1, int lane) {
    float a0 = 0.f, a1 = 0.f;
    for (; e + 4 <= e1; e += 4) {
        int s0 = col[e], s1 = col[e + 1], s2 = col[e + 2], s3 = col[e + 3];
        float2 f0 = __half22float2(H[(size_t)s0 * 64 + lane]);
        float2 f1 = __half22float2(H[(size_t)s1 * 64 + lane]);
        float2 f2 = __half22float2(H[(size_t)s2 * 64 + lane]);
        float2 f3 = __half22float2(H[(size_t)s3 * 64 + lane]);
        a0 += (f0.x + f1.x) + (f2.x + f3.x);
        a1 += (f0.y + f1.y) + (f2.y + f3.y);
    }
    for (; e < e1; e++) {
        float2 f = __half22float2(H[(size_t)col[e] * 64 + lane]);
        a0 += f.x;
        a1 += f.y;
    }
    return make_float2(a0, a1);
}

__global__ void k_spmm1(const float* __restrict__ b1i, const float* __restrict__ b1b) {
    int v = blockIdx.x * 4 + threadIdx.y;
    if (v >= NN) return;
    int lane = threadIdx.x;
    float2 ai = gather_h(g_H1h,  g_col[0], g_rowptr[0][v], g_rowptr[0][v + 1], lane);
    float2 ab = gather_h(g_H1Bh, g_col[1], g_rowptr[1][v], g_rowptr[1][v + 1], lane);
    float n1 = g_norm[1][v], n3 = g_norm[3][v], n0 = g_norm[0][v];
    float h0 = fmaxf(ai.x * n1 + b1i[2 * lane], 0.f) + fmaxf(ab.x * n3 + b1b[2 * lane], 0.f);
    float h1 = fmaxf(ai.y * n1 + b1i[2 * lane + 1], 0.f) + fmaxf(ab.y * n3 + b1b[2 * lane + 1], 0.f);
    *(float2*)&g_H[(size_t)v * 128 + 2 * lane] = make_float2(h0 * n0, h1 * n0);
}

__global__ void k_spmm2(const float* __restrict__ b2, float* __restrict__ out) {
    int v = blockIdx.x * 4 + threadIdx.y;
    if (v >= NN) return;
    int lane = threadIdx.x;
    float2 a = gather_h(g_H1h, g_col[0], g_rowptr[0][v], g_rowptr[0][v + 1], lane);
    float n1 = g_norm[1][v];
    *(float2*)&out[(size_t)v * 128 + 2 * lane] =
        make_float2(a.x * n1 + b2[2 * lane], a.y * n1 + b2[2 * lane + 1]);
}

// ---------------- launch ----------------
extern "C" void kernel_launch(void* const* d_in, const int* in_sizes, int n_in,
                              void* d_out, int out_size) {
    (void)in_sizes; (void)n_in; (void)out_size;
    const float* x    = (const float*)d_in[0];
    const int*   si   = (const int*)d_in[1];
    const int*   di   = (const int*)d_in[2];
    const int*   sb   = (const int*)d_in[3];
    const int*   db   = (const int*)d_in[4];
    const float* W1i  = (const float*)d_in[5];
    const float* b1i  = (const float*)d_in[6];
    const float* W1b  = (const float*)d_in[7];
    const float* b1b  = (const float*)d_in[8];
    const float* W2   = (const float*)d_in[9];
    const float* b2   = (const float*)d_in[10];
    float* out = (float*)d_out;

    const int XS_BYTES = 128 * XS_STRIDE * sizeof(float);   // 67584

    static cudaStream_t s2 = nullptr;
    static cudaEvent_t evF = nullptr, evG = nullptr;
    static int init_done = 0;
    if (!init_done) {   // first (uncaptured) correctness call only
        cudaFuncSetAttribute(k_gemm_mma<0>, cudaFuncAttributeMaxDynamicSharedMemorySize, XS_BYTES);
        cudaFuncSetAttribute(k_gemm_mma<1>, cudaFuncAttributeMaxDynamicSharedMemorySize, XS_BYTES);
        cudaStreamCreateWithFlags(&s2, cudaStreamNonBlocking);
        cudaEventCreateWithFlags(&evF, cudaEventDisableTiming);
        cudaEventCreateWithFlags(&evG, cudaEventDisableTiming);
        init_done = 1;
    }

    const int gblk = (NN + 127) / 128;   // 782
    const dim3 sblk(64, 4);
    const int sgrid = (NN + 3) / 4;      // 25000

    // common prefix (stream 0): counts + norms + packed weights
    k_zero<<<(6 * NN + 255) / 256, 256>>>();
    k_hist<<<(EE + 255) / 256, 256>>>(si, di, sb, db);
    k_prepW<<<(3 * 8192 + 255) / 256, 256>>>(W1i, W1b, W2);
    k_norm<<<(NN + 255) / 256, 256>>>();

    // fork: GEMM<0> on s2, CSR build on stream 0
    cudaEventRecord(evF, 0);
    cudaStreamWaitEvent(s2, evF, 0);
    k_gemm_mma<0><<<dim3(gblk, 2), 256, XS_BYTES, s2>>>(x);   // g_H1h, g_H1Bh

    {
        dim3 ga(NCH, 2);
        k_scanA<<<ga, 256>>>();
        k_scanB<<<2, 128>>>();
        k_scanC<<<ga, CHUNK>>>();
    }
    k_csrfill<<<(EE + 255) / 256, 256>>>(si, di, sb, db);

    // join
    cudaEventRecord(evG, s2);
    cudaStreamWaitEvent(0, evG, 0);

    k_spmm1<<<sgrid, sblk>>>(b1i, b1b);                       // g_H (fp32)
    k_gemm_mma<1><<<dim3(gblk, 1), 256, XS_BYTES>>>(nullptr); // g_H1h = g_H @ W2
    k_spmm2<<<sgrid, sblk>>>(b2, out);
}